// round 16
// baseline (speedup 1.0000x reference)
#include <cuda_runtime.h>
#include <math.h>

// features: [B=16, H=128, W=128, D=8, F=16] float32
// out[b,h,w,d,f] = flip_{W,D}( roll_{(5,-7),(H,W)}( rotate_40deg_NN(x) ) )
//
// Inverse chain per output element:
//   w1 = W-1-w ; d1 = D-1-d                    (undo flips)
//   h2 = (h-5) mod H ; w2 = (w1+7) mod W       (undo roll)
//   (si,sj,valid) = NN inverse-rotation at (h2,w2)
//   out = valid ? x[b, si, sj, d1, f] : 0
//
// R15: champion config (float4, unroll x4 across batches, rotation math
// once per thread, 4 independent LDG.128 + STG.128) with the one unswept
// knob: block size 256 -> 512 (4096 blocks). Same per-thread work, same
// coalescing; fewer wave transitions / CTA launches, slightly lower
// cross-CTA L1tex-queue tail per the B300 spread model.

#define B_ 16
#define H_ 128
#define W_ 128
#define D_ 8
#define F4_ 4                     // F/4
#define N4_ (B_*H_*W_*D_*F4_)     // 8388608 float4 outputs
#define UNROLL_ 4
#define STRIDE_ (N4_/UNROLL_)     // 2097152 float4 = 4 batches
#define BATCH4_ (H_*W_*D_*F4_)    // float4 per batch = 524288
#define THREADS_ 512

__global__ __launch_bounds__(THREADS_) void augment_kernel(
    const float4* __restrict__ in, float4* __restrict__ out,
    float c, float s)
{
    int idx = blockIdx.x * blockDim.x + threadIdx.x;   // 0 .. STRIDE_-1

    // decompose: idx = (((b*H + h)*W + w)*D + d)*F4 + f4   (b in 0..3 here)
    int f4 = idx & 3;
    int t  = idx >> 2;
    int d  = t & 7;   t >>= 3;
    int w  = t & 127; t >>= 7;
    int h  = t & 127;
    int b  = t >> 7;

    // undo flips
    int w1 = (W_ - 1) - w;
    int d1 = (D_ - 1) - d;
    // undo roll (shifts = (5, -7) on (H, W))
    int h2 = h - 5;  if (h2 < 0)    h2 += H_;
    int w2 = w1 + 7; if (w2 >= W_)  w2 -= W_;

    // NN inverse rotation, center 63.5, round-half-to-even (jnp.round)
    float fi = (float)h2 - 63.5f;
    float fj = (float)w2 - 63.5f;
    float src_i =  c * fi + s * fj + 63.5f;
    float src_j = -s * fi + c * fj + 63.5f;
    int si = (int)rintf(src_i);
    int sj = (int)rintf(src_j);

    bool valid = (si >= 0) & (si < H_) & (sj >= 0) & (sj < W_);

    float4 v[UNROLL_];
    if (valid) {
        int src = (((b * H_ + si) * W_ + sj) * D_ + d1) * F4_ + f4;
        #pragma unroll
        for (int k = 0; k < UNROLL_; k++)
            v[k] = in[src + k * (4 * BATCH4_)];
    } else {
        #pragma unroll
        for (int k = 0; k < UNROLL_; k++)
            v[k] = make_float4(0.f, 0.f, 0.f, 0.f);
    }

    #pragma unroll
    for (int k = 0; k < UNROLL_; k++)
        out[idx + k * STRIDE_] = v[k];
}

extern "C" void kernel_launch(void* const* d_in, const int* in_sizes, int n_in,
                              void* d_out, int out_size) {
    const float4* in = (const float4*)d_in[0];
    float4* out = (float4*)d_out;

    const double theta = 40.0 * 3.14159265358979323846 / 180.0;
    const float c = (float)cos(theta);
    const float s = (float)sin(theta);

    const int blocks = STRIDE_ / THREADS_;   // 4096
    augment_kernel<<<blocks, THREADS_>>>(in, out, c, s);
}